// round 4
// baseline (speedup 1.0000x reference)
#include <cuda_runtime.h>
#include <math.h>

// AdderNet, packed-f32x2 implementation.
// out = -sum |patch - w|; per layer affine+relu; final log_softmax.
#define B 4096

typedef unsigned long long ull;
#define ABSM 0x7FFFFFFF7FFFFFFFULL

__device__ __forceinline__ ull add2(ull a, ull b) {
    ull r; asm("add.rn.f32x2 %0,%1,%2;" : "=l"(r) : "l"(a), "l"(b)); return r;
}
__device__ __forceinline__ ull dup2(float v) {
    ull r; asm("mov.b64 %0,{%1,%1};" : "=l"(r) : "f"(v)); return r;
}
__device__ __forceinline__ float lo32(ull a) { return __uint_as_float((unsigned)a); }
__device__ __forceinline__ float hi32(ull a) { return __uint_as_float((unsigned)(a >> 32)); }

__device__ float g_a1[B * 16 * 13 * 13];   // 44.3 MB
__device__ float g_a2[B * 32 * 7 * 7];     // 25.7 MB

// ---------------------------------------------------------------------------
// Layer 1: x[B,1,28,28] (-0.5) -> a1[B,16,13,13], s2 p0. relu((10-sum)/4).
// Thread per output pixel; 9-elem patch in regs; 16 outs as 8 packed accs.
// Weights negated+transposed in smem: wt[p*16+o] = -w1[o*9+p].
// ---------------------------------------------------------------------------
__global__ __launch_bounds__(256) void k_layer1(const float* __restrict__ x,
                                                const float* __restrict__ w1,
                                                float* __restrict__ a1) {
    __shared__ __align__(16) float wt[9 * 16];
    int t = threadIdx.x;
    if (t < 144) { int o = t / 9, p = t % 9; wt[p * 16 + o] = -w1[t]; }
    __syncthreads();

    int idx = blockIdx.x * 256 + t;     // exact: 4096*169 / 256 = 2704 blocks
    int b = idx / 169;
    int pix = idx % 169;
    int py = pix / 13, px = pix % 13;
    const float* xb = x + b * 784;

    float patch[9];
#pragma unroll
    for (int kh = 0; kh < 3; kh++)
#pragma unroll
        for (int kw = 0; kw < 3; kw++)
            patch[kh * 3 + kw] = xb[(py * 2 + kh) * 28 + (px * 2 + kw)] - 0.5f;

    ull acc[8];
#pragma unroll
    for (int j = 0; j < 8; j++) acc[j] = 0ULL;

#pragma unroll
    for (int p = 0; p < 9; p++) {
        ull va = dup2(patch[p]);
#pragma unroll
        for (int j = 0; j < 8; j++) {
            ull w = *(const ull*)(wt + p * 16 + j * 2);
            ull d = add2(va, w) & ABSM;
            acc[j] = add2(acc[j], d);
        }
    }

    float* out = a1 + b * 2704 + pix;
#pragma unroll
    for (int j = 0; j < 8; j++) {
        out[(2 * j) * 169]     = fmaxf((10.0f - lo32(acc[j])) * 0.25f, 0.0f);
        out[(2 * j + 1) * 169] = fmaxf((10.0f - hi32(acc[j])) * 0.25f, 0.0f);
    }
}

// ---------------------------------------------------------------------------
// Layer 2 (70% of flops): a1[B,16,13,13] -> a2[B,32,7,7], s2 p1.
// relu((130-sum)/8). CTA = 1 image, 224 thr = 28 pixel-pairs x 8 out-groups.
// Thread: 2 pixels (py0, py0+1 along y; row 7 = padding) x 4 outputs
// (2 packed pairs). Input tile 16x17x15 zero-padded; weights negated +
// transposed: wt[(c*9+k)*32+o] = -w2[o*144+c*9+k].
// Per (c,k): 2 LDS.32 + 2 LDS.64 + 2 pack + 8 FADD2 + 8 LOP3 for 16 pairs.
// ---------------------------------------------------------------------------
__global__ __launch_bounds__(224) void k_layer2(const float* __restrict__ a1,
                                                const float* __restrict__ w2,
                                                float* __restrict__ a2) {
    __shared__ __align__(16) float sp[16 * 17 * 15];   // 4080 f
    __shared__ __align__(16) float wt[32 * 144];       // 4608 f

    int t = threadIdx.x;
    int b = blockIdx.x;

    for (int i = t; i < 4080; i += 224) sp[i] = 0.0f;
    __syncthreads();
    const float* src = a1 + b * 2704;
    for (int i = t; i < 2704; i += 224) {
        int c = i / 169, r = i % 169, y = r / 13, xx = r % 13;
        sp[c * 255 + (y + 1) * 15 + (xx + 1)] = src[i];
    }
    for (int i = t; i < 4608; i += 224) {
        int o = i / 144, r = i % 144;
        wt[r * 32 + o] = -w2[i];
    }
    __syncthreads();

    int og4 = (t / 28) * 4;             // output base: 0,4,...,28
    int pairidx = t % 28;
    int px = pairidx % 7;
    int py0 = (pairidx / 7) * 2;        // 0,2,4,6; second pixel py0+1 (7 = pad)
    const float* base = sp + (py0 * 2) * 15 + px * 2;
    const float* wp = wt + og4;

    ull a00 = 0, a01 = 0, a10 = 0, a11 = 0;

#pragma unroll 2
    for (int c = 0; c < 16; c++) {
        const float* pc = base + c * 255;
        const float* wc = wp + c * 288;  // c*9*32
#pragma unroll
        for (int k = 0; k < 9; k++) {
            int off = (k / 3) * 15 + (k % 3);
            float v0 = pc[off];
            float v1 = pc[off + 30];
            ull va0 = dup2(v0), va1 = dup2(v1);
            ull w01 = *(const ull*)(wc + k * 32);
            ull w23 = *(const ull*)(wc + k * 32 + 2);
            ull d;
            d = add2(va0, w01) & ABSM; a00 = add2(a00, d);
            d = add2(va0, w23) & ABSM; a01 = add2(a01, d);
            d = add2(va1, w01) & ABSM; a10 = add2(a10, d);
            d = add2(va1, w23) & ABSM; a11 = add2(a11, d);
        }
    }

    float* outb = a2 + b * 1568;
    int p0 = py0 * 7 + px;
    outb[(og4 + 0) * 49 + p0] = fmaxf((130.0f - lo32(a00)) * 0.125f, 0.0f);
    outb[(og4 + 1) * 49 + p0] = fmaxf((130.0f - hi32(a00)) * 0.125f, 0.0f);
    outb[(og4 + 2) * 49 + p0] = fmaxf((130.0f - lo32(a01)) * 0.125f, 0.0f);
    outb[(og4 + 3) * 49 + p0] = fmaxf((130.0f - hi32(a01)) * 0.125f, 0.0f);
    if (py0 + 1 < 7) {
        int p1 = p0 + 7;
        outb[(og4 + 0) * 49 + p1] = fmaxf((130.0f - lo32(a10)) * 0.125f, 0.0f);
        outb[(og4 + 1) * 49 + p1] = fmaxf((130.0f - hi32(a10)) * 0.125f, 0.0f);
        outb[(og4 + 2) * 49 + p1] = fmaxf((130.0f - lo32(a11)) * 0.125f, 0.0f);
        outb[(og4 + 3) * 49 + p1] = fmaxf((130.0f - hi32(a11)) * 0.125f, 0.0f);
    }
}

// ---------------------------------------------------------------------------
// Fused Layer 3 + Layer 4 + log_softmax.
// L3: a2[B,32,7,7] -> a3[16,4,4] (smem), s2 p1, relu((280-sum)/16).
// L4: a3 -> 10 logits (k3 s2 p0 on 4x4 -> 1x1), then log_softmax.
// CTA = 4 images, 128 threads; warp w owns image w (a3 stays warp-local).
// L3 thread: 2 pixels x 4 outputs packed (8 pairidx x 4 og = 32 thr/img).
// L4: 30 lanes = 10 outputs x 3 kh-rows, shuffle-reduced.
// Dynamic smem: sp[4*2592] | wt3[4608] | ws4[1440] | a3s[4*256]  (~70KB).
// ---------------------------------------------------------------------------
__global__ __launch_bounds__(128) void k_layer34(const float* __restrict__ a2,
                                                 const float* __restrict__ w3,
                                                 const float* __restrict__ w4,
                                                 float* __restrict__ out) {
    extern __shared__ __align__(16) float dyn[];
    float* sp  = dyn;            // 4*2592 = 10368
    float* wt  = sp + 10368;     // 4608, wt[(c*9+k)*16+o] = -w3[o*288+c*9+k]
    float* ws4 = wt + 4608;      // 1440
    float* a3s = ws4 + 1440;     // 4*256
    __shared__ float lg[4][10];

    int t = threadIdx.x;
    int b0 = blockIdx.x * 4;

    for (int i = t; i < 10368; i += 128) sp[i] = 0.0f;
    __syncthreads();
    for (int i = t; i < 4 * 1568; i += 128) {
        int img = i / 1568, r = i % 1568;
        int c = r / 49, q = r % 49, y = q / 7, xx = q % 7;
        sp[img * 2592 + c * 81 + (y + 1) * 9 + (xx + 1)] = a2[(b0 + img) * 1568 + r];
    }
    for (int i = t; i < 4608; i += 128) {
        int o = i / 288, r = i % 288;
        wt[r * 16 + o] = -w3[i];
    }
    for (int i = t; i < 1440; i += 128) ws4[i] = w4[i];
    __syncthreads();

    int img = t >> 5;
    int sub = t & 31;

    // ---- Layer 3 ----
    int og4 = (sub >> 3) * 4;           // 0,4,8,12
    int pairidx = sub & 7;
    int px = pairidx & 3;
    int py0 = (pairidx >> 2) * 2;       // 0 or 2; both rows valid (4x4 out)
    const float* base = sp + img * 2592 + (py0 * 2) * 9 + px * 2;
    const float* wp = wt + og4;

    ull a00 = 0, a01 = 0, a10 = 0, a11 = 0;
#pragma unroll 2
    for (int c = 0; c < 32; c++) {
        const float* pc = base + c * 81;
        const float* wc = wp + c * 144;  // c*9*16
#pragma unroll
        for (int k = 0; k < 9; k++) {
            int off = (k / 3) * 9 + (k % 3);
            float v0 = pc[off];
            float v1 = pc[off + 18];
            ull va0 = dup2(v0), va1 = dup2(v1);
            ull w01 = *(const ull*)(wc + k * 16);
            ull w23 = *(const ull*)(wc + k * 16 + 2);
            ull d;
            d = add2(va0, w01) & ABSM; a00 = add2(a00, d);
            d = add2(va0, w23) & ABSM; a01 = add2(a01, d);
            d = add2(va1, w01) & ABSM; a10 = add2(a10, d);
            d = add2(va1, w23) & ABSM; a11 = add2(a11, d);
        }
    }

    float* a3i = a3s + img * 256;
    int q0 = py0 * 4 + px;
    a3i[(og4 + 0) * 16 + q0] = fmaxf((280.0f - lo32(a00)) * 0.0625f, 0.0f);
    a3i[(og4 + 1) * 16 + q0] = fmaxf((280.0f - hi32(a00)) * 0.0625f, 0.0f);
    a3i[(og4 + 2) * 16 + q0] = fmaxf((280.0f - lo32(a01)) * 0.0625f, 0.0f);
    a3i[(og4 + 3) * 16 + q0] = fmaxf((280.0f - hi32(a01)) * 0.0625f, 0.0f);
    int q1 = q0 + 4;
    a3i[(og4 + 0) * 16 + q1] = fmaxf((280.0f - lo32(a10)) * 0.0625f, 0.0f);
    a3i[(og4 + 1) * 16 + q1] = fmaxf((280.0f - hi32(a10)) * 0.0625f, 0.0f);
    a3i[(og4 + 2) * 16 + q1] = fmaxf((280.0f - lo32(a11)) * 0.0625f, 0.0f);
    a3i[(og4 + 3) * 16 + q1] = fmaxf((280.0f - hi32(a11)) * 0.0625f, 0.0f);
    __syncwarp();   // a3 is produced and consumed entirely within this warp

    // ---- Layer 4 ----
    float s = 0.0f;
    if (sub < 30) {
        int o = sub / 3;
        int kh = sub - o * 3;
        const float* xp = a3i + kh * 4;          // y = kh (s2 p0, 1x1 out)
        const float* wq = ws4 + o * 144 + kh * 3;
#pragma unroll
        for (int c = 0; c < 16; c++)
#pragma unroll
            for (int kw = 0; kw < 3; kw++)
                s += fabsf(xp[c * 16 + kw] - wq[c * 9 + kw]);
    }
    float s1 = __shfl_down_sync(0xffffffffu, s, 1);
    float s2 = __shfl_down_sync(0xffffffffu, s, 2);
    if (sub < 30 && sub % 3 == 0) lg[img][sub / 3] = -(s + s1 + s2);
    __syncwarp();

    float logit = (sub < 10) ? lg[img][sub] : -1e30f;
    float m = logit;
#pragma unroll
    for (int off = 16; off; off >>= 1)
        m = fmaxf(m, __shfl_xor_sync(0xffffffffu, m, off));
    float e = (sub < 10) ? expf(logit - m) : 0.0f;
    float sum = e;
#pragma unroll
    for (int off = 16; off; off >>= 1)
        sum += __shfl_xor_sync(0xffffffffu, sum, off);

    if (sub < 10) out[(b0 + img) * 10 + sub] = logit - m - logf(sum);
}

// ---------------------------------------------------------------------------
extern "C" void kernel_launch(void* const* d_in, const int* in_sizes, int n_in,
                              void* d_out, int out_size) {
    const float* x  = (const float*)d_in[0];
    const float* w1 = (const float*)d_in[1];
    const float* w2 = (const float*)d_in[2];
    const float* w3 = (const float*)d_in[3];
    const float* w4 = (const float*)d_in[4];
    float* out = (float*)d_out;

    float *a1, *a2;
    cudaGetSymbolAddress((void**)&a1, g_a1);
    cudaGetSymbolAddress((void**)&a2, g_a2);

    const int smem34 = (10368 + 4608 + 1440 + 1024) * 4;   // 69760 B
    cudaFuncSetAttribute(k_layer34, cudaFuncAttributeMaxDynamicSharedMemorySize,
                         smem34);

    k_layer1<<<2704, 256>>>(x, w1, a1);
    k_layer2<<<B, 224>>>(a1, w2, a2);
    k_layer34<<<B / 4, 128, smem34>>>(a2, w3, w4, out);
}

// round 5
// speedup vs baseline: 1.9679x; 1.9679x over previous
#include <cuda_runtime.h>
#include <math.h>

// AdderNet, batch-minor packed-f32x2 implementation.
// Intermediates: [channel*pixel][B] so each lane owns 4 consecutive images.
#define B 4096
typedef unsigned long long ull;
#define ABSM 0x7FFFFFFF7FFFFFFFULL

__device__ __forceinline__ ull add2(ull a, ull b) {
    ull r; asm("add.rn.f32x2 %0,%1,%2;" : "=l"(r) : "l"(a), "l"(b)); return r;
}
__device__ __forceinline__ ull dup2(float v) {
    ull r; asm("mov.b64 %0,{%1,%1};" : "=l"(r) : "f"(v)); return r;
}
__device__ __forceinline__ ull pk2(float a, float b) {
    ull r; asm("mov.b64 %0,{%1,%2};" : "=l"(r) : "f"(a), "f"(b)); return r;
}
__device__ __forceinline__ float lo32(ull a) { return __uint_as_float((unsigned)a); }
__device__ __forceinline__ float hi32(ull a) { return __uint_as_float((unsigned)(a >> 32)); }
// acc += |v + wneg|   (wneg pre-negated so FADD2 computes v-w)
__device__ __forceinline__ ull accabs(ull acc, ull v, ull wneg) {
    return add2(acc, add2(v, wneg) & ABSM);
}

__device__ float g_a1[16 * 169 * B];   // 44.3 MB  [(c*169+pix)][b]
__device__ float g_a2[32 * 49 * B];    // 25.7 MB  [(o*49+pix)][b]
__device__ float g_a3[16 * 16 * B];    //  4.2 MB  [(o*16+q)][b]

// ---------------------------------------------------------------------------
// Layer 1: x[b][28*28] (-0.5) -> a1[(c*169+pix)][b], s2 p0, relu((10-s)/4).
// CTA = 16 images; smem transpose xs[p][18] (pad-18 kills bank conflicts,
// keeps 8B alignment). Thread = (pix-slot, image-pair); 16 channel accs.
// ---------------------------------------------------------------------------
__global__ __launch_bounds__(256) void k_layer1(const float* __restrict__ x,
                                                const float* __restrict__ w1,
                                                float* __restrict__ a1) {
    extern __shared__ float dyn[];
    float* xs = dyn;                         // [784][18]
    ull* wn = (ull*)(dyn + 784 * 18);        // [k*16+o] = dup2(-w1[o*9+k])

    int t = threadIdx.x;
    int b0 = blockIdx.x * 16;
    if (t < 144) { int o = t / 9, k = t % 9; wn[k * 16 + o] = dup2(-w1[t]); }
    for (int i = t; i < 784 * 16; i += 256) {
        int img = i / 784, p = i - img * 784;
        xs[p * 18 + img] = x[(b0 + img) * 784 + p] - 0.5f;
    }
    __syncthreads();

    int i2 = t & 7;           // image pair: b0+2*i2, b0+2*i2+1
    int slot = t >> 3;        // 32 pixel slots
    for (int pass = 0; pass < 6; pass++) {
        int pix = pass * 32 + slot;
        if (pix >= 169) break;
        int py = pix / 13, px = pix - py * 13;

        ull v[9];
#pragma unroll
        for (int kh = 0; kh < 3; kh++)
#pragma unroll
            for (int kw = 0; kw < 3; kw++)
                v[kh * 3 + kw] =
                    *(const ull*)&xs[((py * 2 + kh) * 28 + px * 2 + kw) * 18 + i2 * 2];

        ull acc[16];
#pragma unroll
        for (int c = 0; c < 16; c++) acc[c] = 0ULL;
#pragma unroll
        for (int k = 0; k < 9; k++) {
            const ulonglong2* wr = (const ulonglong2*)&wn[k * 16];
#pragma unroll
            for (int c2 = 0; c2 < 8; c2++) {
                ulonglong2 w = wr[c2];
                acc[2 * c2]     = accabs(acc[2 * c2],     v[k], w.x);
                acc[2 * c2 + 1] = accabs(acc[2 * c2 + 1], v[k], w.y);
            }
        }

        float* op = a1 + pix * B + b0 + i2 * 2;
#pragma unroll
        for (int c = 0; c < 16; c++) {
            float f0 = fmaxf((10.0f - lo32(acc[c])) * 0.25f, 0.0f);
            float f1 = fmaxf((10.0f - hi32(acc[c])) * 0.25f, 0.0f);
            *(ull*)(op + c * (169 * B)) = pk2(f0, f1);
        }
    }
}

// ---------------------------------------------------------------------------
// Layer 2 (70% of flops): a1 -> a2, s2 p1, relu((130-s)/8).
// Grid (imgg=32, pixg=7, ob=2); CTA 224 thr = 7 warps. Warp = 1 out-pixel;
// lane = 4 images (one ull2 load). 16-output half staged as dup'd -w in smem.
// Per (c,k): 1 LDG.128 + 8 LDS.128(bcast) + 96 math for 64 pairs.
// ---------------------------------------------------------------------------
__global__ __launch_bounds__(224, 2) void k_layer2(const float* __restrict__ a1,
                                                   const float* __restrict__ w2,
                                                   float* __restrict__ a2) {
    __shared__ ull wn[2304];   // [(c*9+k)*16 + j] = dup2(-w2[(ob*16+j)*144 + c*9+k])
    int t = threadIdx.x;
    int imgg = blockIdx.x, pixg = blockIdx.y, ob = blockIdx.z;
    for (int i = t; i < 2304; i += 224) {
        int r = i >> 4, j = i & 15;
        wn[i] = dup2(-w2[(ob * 16 + j) * 144 + r]);
    }
    __syncthreads();

    int warp = t >> 5, lane = t & 31;
    int pix = pixg * 7 + warp;
    int py = pix / 7, px = pix - py * 7;       // warp-uniform
    int b = imgg * 128 + lane * 4;

    int off[9];
#pragma unroll
    for (int kh = 0; kh < 3; kh++)
#pragma unroll
        for (int kw = 0; kw < 3; kw++) {
            int iy = py * 2 - 1 + kh, ix = px * 2 - 1 + kw;
            off[kh * 3 + kw] =
                (iy >= 0 && iy < 13 && ix >= 0 && ix < 13) ? (iy * 13 + ix) * B : -1;
        }

    ull s0[16], s1[16];
#pragma unroll
    for (int j = 0; j < 16; j++) { s0[j] = 0ULL; s1[j] = 0ULL; }

    const float* base = a1 + b;
#pragma unroll 1
    for (int c = 0; c < 16; c++) {
        ull v0[9], v1[9];
#pragma unroll
        for (int k = 0; k < 9; k++) {
            if (off[k] >= 0) {
                ulonglong2 vv = *(const ulonglong2*)(base + c * (169 * B) + off[k]);
                v0[k] = vv.x; v1[k] = vv.y;
            } else { v0[k] = 0ULL; v1[k] = 0ULL; }
        }
#pragma unroll
        for (int k = 0; k < 9; k++) {
            const ulonglong2* wr = (const ulonglong2*)&wn[(c * 9 + k) * 16];
#pragma unroll
            for (int j2 = 0; j2 < 8; j2++) {
                ulonglong2 w = wr[j2];
                s0[2 * j2]     = accabs(s0[2 * j2],     v0[k], w.x);
                s1[2 * j2]     = accabs(s1[2 * j2],     v1[k], w.x);
                s0[2 * j2 + 1] = accabs(s0[2 * j2 + 1], v0[k], w.y);
                s1[2 * j2 + 1] = accabs(s1[2 * j2 + 1], v1[k], w.y);
            }
        }
    }

    float* op = a2 + ((ob * 16) * 49 + pix) * B + b;
#pragma unroll
    for (int j = 0; j < 16; j++) {
        float4 o;
        o.x = fmaxf((130.0f - lo32(s0[j])) * 0.125f, 0.0f);
        o.y = fmaxf((130.0f - hi32(s0[j])) * 0.125f, 0.0f);
        o.z = fmaxf((130.0f - lo32(s1[j])) * 0.125f, 0.0f);
        o.w = fmaxf((130.0f - hi32(s1[j])) * 0.125f, 0.0f);
        *(float4*)(op + j * (49 * B)) = o;
    }
}

// ---------------------------------------------------------------------------
// Layer 3: a2 -> a3, s2 p1, relu((280-s)/16).
// Grid (imgg=32, qg=4, ob=2); CTA 128 thr = 4 warps; warp = 1 out-pixel q,
// lane = 4 images; 8-output half per CTA.
// ---------------------------------------------------------------------------
__global__ __launch_bounds__(128) void k_layer3(const float* __restrict__ a2,
                                                const float* __restrict__ w3,
                                                float* __restrict__ a3) {
    __shared__ ull wn[2304];   // [(c*9+k)*8 + j] = dup2(-w3[(ob*8+j)*288 + c*9+k])
    int t = threadIdx.x;
    int imgg = blockIdx.x, qg = blockIdx.y, ob = blockIdx.z;
    for (int i = t; i < 2304; i += 128) {
        int r = i >> 3, j = i & 7;
        wn[i] = dup2(-w3[(ob * 8 + j) * 288 + r]);
    }
    __syncthreads();

    int warp = t >> 5, lane = t & 31;
    int q = qg * 4 + warp;
    int qy = q >> 2, qx = q & 3;
    int b = imgg * 128 + lane * 4;

    int off[9];
#pragma unroll
    for (int kh = 0; kh < 3; kh++)
#pragma unroll
        for (int kw = 0; kw < 3; kw++) {
            int iy = qy * 2 - 1 + kh, ix = qx * 2 - 1 + kw;
            off[kh * 3 + kw] =
                (iy >= 0 && iy < 7 && ix >= 0 && ix < 7) ? (iy * 7 + ix) * B : -1;
        }

    ull s0[8], s1[8];
#pragma unroll
    for (int j = 0; j < 8; j++) { s0[j] = 0ULL; s1[j] = 0ULL; }

    const float* base = a2 + b;
#pragma unroll 1
    for (int c = 0; c < 32; c++) {
        ull v0[9], v1[9];
#pragma unroll
        for (int k = 0; k < 9; k++) {
            if (off[k] >= 0) {
                ulonglong2 vv = *(const ulonglong2*)(base + c * (49 * B) + off[k]);
                v0[k] = vv.x; v1[k] = vv.y;
            } else { v0[k] = 0ULL; v1[k] = 0ULL; }
        }
#pragma unroll
        for (int k = 0; k < 9; k++) {
            const ulonglong2* wr = (const ulonglong2*)&wn[(c * 9 + k) * 8];
#pragma unroll
            for (int j2 = 0; j2 < 4; j2++) {
                ulonglong2 w = wr[j2];
                s0[2 * j2]     = accabs(s0[2 * j2],     v0[k], w.x);
                s1[2 * j2]     = accabs(s1[2 * j2],     v1[k], w.x);
                s0[2 * j2 + 1] = accabs(s0[2 * j2 + 1], v0[k], w.y);
                s1[2 * j2 + 1] = accabs(s1[2 * j2 + 1], v1[k], w.y);
            }
        }
    }

    float* op = a3 + ((ob * 8) * 16 + q) * B + b;
#pragma unroll
    for (int j = 0; j < 8; j++) {
        float4 o;
        o.x = fmaxf((280.0f - lo32(s0[j])) * 0.0625f, 0.0f);
        o.y = fmaxf((280.0f - hi32(s0[j])) * 0.0625f, 0.0f);
        o.z = fmaxf((280.0f - lo32(s1[j])) * 0.0625f, 0.0f);
        o.w = fmaxf((280.0f - hi32(s1[j])) * 0.0625f, 0.0f);
        *(float4*)(op + j * (16 * B)) = o;
    }
}

// ---------------------------------------------------------------------------
// Layer 4 + log_softmax: a3 -> out[b][10]. Patch = rows/cols 0..2 of 4x4.
// Thread = 2 images (1 ull); 10 packed accs; per-thread softmax, ull stores.
// ---------------------------------------------------------------------------
__global__ __launch_bounds__(256) void k_layer4(const float* __restrict__ a3,
                                                const float* __restrict__ w4,
                                                float* __restrict__ out) {
    __shared__ ull wn[1440];   // [(c*9+k)*10 + o] = dup2(-w4[o*144 + c*9+k])
    int t = threadIdx.x;
    for (int i = t; i < 1440; i += 256) {
        int r = i / 10, o = i - r * 10;
        wn[i] = dup2(-w4[o * 144 + r]);
    }
    __syncthreads();

    int b = (blockIdx.x * 256 + t) * 2;
    ull acc[10];
#pragma unroll
    for (int o = 0; o < 10; o++) acc[o] = 0ULL;

    const float* base = a3 + b;
#pragma unroll 2
    for (int c = 0; c < 16; c++) {
#pragma unroll
        for (int kh = 0; kh < 3; kh++)
#pragma unroll
            for (int kw = 0; kw < 3; kw++) {
                ull v = *(const ull*)(base + (c * 16 + kh * 4 + kw) * B);
                const ull* wr = &wn[(c * 9 + kh * 3 + kw) * 10];
#pragma unroll
                for (int o2 = 0; o2 < 5; o2++) {
                    ulonglong2 w = *(const ulonglong2*)&wr[o2 * 2];
                    acc[2 * o2]     = accabs(acc[2 * o2],     v, w.x);
                    acc[2 * o2 + 1] = accabs(acc[2 * o2 + 1], v, w.y);
                }
            }
    }

    float l0[10], l1[10];
#pragma unroll
    for (int o = 0; o < 10; o++) { l0[o] = -lo32(acc[o]); l1[o] = -hi32(acc[o]); }
    float m0 = l0[0], m1 = l1[0];
#pragma unroll
    for (int o = 1; o < 10; o++) { m0 = fmaxf(m0, l0[o]); m1 = fmaxf(m1, l1[o]); }
    float e0 = 0.0f, e1 = 0.0f;
#pragma unroll
    for (int o = 0; o < 10; o++) { e0 += expf(l0[o] - m0); e1 += expf(l1[o] - m1); }
    float d0 = m0 + logf(e0), d1 = m1 + logf(e1);

    ull* op0 = (ull*)(out + b * 10);
    ull* op1 = (ull*)(out + (b + 1) * 10);
#pragma unroll
    for (int o2 = 0; o2 < 5; o2++) {
        op0[o2] = pk2(l0[2 * o2] - d0, l0[2 * o2 + 1] - d0);
        op1[o2] = pk2(l1[2 * o2] - d1, l1[2 * o2 + 1] - d1);
    }
}

// ---------------------------------------------------------------------------
extern "C" void kernel_launch(void* const* d_in, const int* in_sizes, int n_in,
                              void* d_out, int out_size) {
    const float* x  = (const float*)d_in[0];
    const float* w1 = (const float*)d_in[1];
    const float* w2 = (const float*)d_in[2];
    const float* w3 = (const float*)d_in[3];
    const float* w4 = (const float*)d_in[4];
    float* out = (float*)d_out;

    float *a1, *a2, *a3;
    cudaGetSymbolAddress((void**)&a1, g_a1);
    cudaGetSymbolAddress((void**)&a2, g_a2);
    cudaGetSymbolAddress((void**)&a3, g_a3);

    const int smem1 = 784 * 18 * 4 + 144 * 8;   // 57600 B
    cudaFuncSetAttribute(k_layer1, cudaFuncAttributeMaxDynamicSharedMemorySize,
                         smem1);

    k_layer1<<<B / 16, 256, smem1>>>(x, w1, a1);
    k_layer2<<<dim3(32, 7, 2), 224>>>(a1, w2, a2);
    k_layer3<<<dim3(32, 4, 2), 128>>>(a2, w3, a3);
    k_layer4<<<B / 512, 256>>>(a3, w4, out);
}

// round 6
// speedup vs baseline: 2.1686x; 1.1020x over previous
#include <cuda_runtime.h>
#include <math.h>

// AdderNet, batch-minor packed-f32x2. Intermediates [channel*pixel][B].
#define B 4096
typedef unsigned long long ull;
#define ABSM 0x7FFFFFFF7FFFFFFFULL

__device__ __forceinline__ ull add2(ull a, ull b) {
    ull r; asm("add.rn.f32x2 %0,%1,%2;" : "=l"(r) : "l"(a), "l"(b)); return r;
}
__device__ __forceinline__ ull dup2(float v) {
    ull r; asm("mov.b64 %0,{%1,%1};" : "=l"(r) : "f"(v)); return r;
}
__device__ __forceinline__ ull pk2(float a, float b) {
    ull r; asm("mov.b64 %0,{%1,%2};" : "=l"(r) : "f"(a), "f"(b)); return r;
}
__device__ __forceinline__ float lo32(ull a) { return __uint_as_float((unsigned)a); }
__device__ __forceinline__ float hi32(ull a) { return __uint_as_float((unsigned)(a >> 32)); }
__device__ __forceinline__ ull accabs(ull acc, ull v, ull wneg) {
    return add2(acc, add2(v, wneg) & ABSM);
}

__device__ float g_a1[16 * 169 * B];   // [(c*169+pix)][b]
__device__ float g_a2[32 * 49 * B];    // [(o*49+pix)][b]
__device__ float g_a3[16 * 16 * B];    // [(o*16+q)][b]

// ---------------------------------------------------------------------------
// Layer 1: x[b][784] (-0.5) -> a1, s2 p0, relu((10-s)/4).
// CTA = 16 images; smem transpose xs[p][18]; thread = (pixel-slot, img-pair).
// ---------------------------------------------------------------------------
__global__ __launch_bounds__(256) void k_layer1(const float* __restrict__ x,
                                                const float* __restrict__ w1,
                                                float* __restrict__ a1) {
    extern __shared__ float dyn[];
    float* xs = dyn;                         // [784][18]
    ull* wn = (ull*)(dyn + 784 * 18);        // [k*16+o] = dup2(-w1[o*9+k])

    int t = threadIdx.x;
    int b0 = blockIdx.x * 16;
    if (t < 144) { int o = t / 9, k = t % 9; wn[k * 16 + o] = dup2(-w1[t]); }
    for (int i = t; i < 784 * 16; i += 256) {
        int img = i / 784, p = i - img * 784;
        xs[p * 18 + img] = x[(b0 + img) * 784 + p] - 0.5f;
    }
    __syncthreads();

    int i2 = t & 7;
    int slot = t >> 3;
    for (int pass = 0; pass < 6; pass++) {
        int pix = pass * 32 + slot;
        if (pix >= 169) break;
        int py = pix / 13, px = pix - py * 13;

        ull v[9];
#pragma unroll
        for (int kh = 0; kh < 3; kh++)
#pragma unroll
            for (int kw = 0; kw < 3; kw++)
                v[kh * 3 + kw] =
                    *(const ull*)&xs[((py * 2 + kh) * 28 + px * 2 + kw) * 18 + i2 * 2];

        ull acc[16];
#pragma unroll
        for (int c = 0; c < 16; c++) acc[c] = 0ULL;
#pragma unroll
        for (int k = 0; k < 9; k++) {
            const ulonglong2* wr = (const ulonglong2*)&wn[k * 16];
#pragma unroll
            for (int c2 = 0; c2 < 8; c2++) {
                ulonglong2 w = wr[c2];
                acc[2 * c2]     = accabs(acc[2 * c2],     v[k], w.x);
                acc[2 * c2 + 1] = accabs(acc[2 * c2 + 1], v[k], w.y);
            }
        }

        float* op = a1 + pix * B + b0 + i2 * 2;
#pragma unroll
        for (int c = 0; c < 16; c++) {
            float f0 = fmaxf((10.0f - lo32(acc[c])) * 0.25f, 0.0f);
            float f1 = fmaxf((10.0f - hi32(acc[c])) * 0.25f, 0.0f);
            *(ull*)(op + c * (169 * B)) = pk2(f0, f1);
        }
    }
}

// ---------------------------------------------------------------------------
// Layer 2: a1 -> a2, s2 p1, relu((130-s)/8).
// Grid (imgg=64, pixg=7, ob=2), CTA 224 = 7 warps; warp = 1 out-pixel,
// lane = 2 images (LDG.64, 256B/warp coalesced). 16 outs -> 16 ull accs.
// ---------------------------------------------------------------------------
__global__ __launch_bounds__(224, 3) void k_layer2(const float* __restrict__ a1,
                                                   const float* __restrict__ w2,
                                                   float* __restrict__ a2) {
    __shared__ __align__(16) ull wn[2304];  // [(c*9+k)*16+j] = dup2(-w2[(ob*16+j)*144+c*9+k])
    int t = threadIdx.x;
    int imgg = blockIdx.x, pixg = blockIdx.y, ob = blockIdx.z;
    for (int i = t; i < 2304; i += 224) {
        int r = i >> 4, j = i & 15;
        wn[i] = dup2(-w2[(ob * 16 + j) * 144 + r]);
    }
    __syncthreads();

    int warp = t >> 5, lane = t & 31;
    int pix = pixg * 7 + warp;
    int py = pix / 7, px = pix - py * 7;
    int b = imgg * 64 + lane * 2;

    int off[9];
#pragma unroll
    for (int kh = 0; kh < 3; kh++)
#pragma unroll
        for (int kw = 0; kw < 3; kw++) {
            int iy = py * 2 - 1 + kh, ix = px * 2 - 1 + kw;
            off[kh * 3 + kw] =
                (iy >= 0 && iy < 13 && ix >= 0 && ix < 13) ? (iy * 13 + ix) * B : -1;
        }

    ull s[16];
#pragma unroll
    for (int j = 0; j < 16; j++) s[j] = 0ULL;

    const float* base = a1 + b;
#pragma unroll 1
    for (int c = 0; c < 16; c++) {
        ull v[9];
#pragma unroll
        for (int k = 0; k < 9; k++)
            v[k] = (off[k] >= 0) ? *(const ull*)(base + c * (169 * B) + off[k]) : 0ULL;
#pragma unroll
        for (int k = 0; k < 9; k++) {
            const ulonglong2* wr = (const ulonglong2*)&wn[(c * 9 + k) * 16];
#pragma unroll
            for (int j2 = 0; j2 < 8; j2++) {
                ulonglong2 w = wr[j2];
                s[2 * j2]     = accabs(s[2 * j2],     v[k], w.x);
                s[2 * j2 + 1] = accabs(s[2 * j2 + 1], v[k], w.y);
            }
        }
    }

    float* op = a2 + ((ob * 16) * 49 + pix) * B + b;
#pragma unroll
    for (int j = 0; j < 16; j++) {
        float f0 = fmaxf((130.0f - lo32(s[j])) * 0.125f, 0.0f);
        float f1 = fmaxf((130.0f - hi32(s[j])) * 0.125f, 0.0f);
        *(ull*)(op + j * (49 * B)) = pk2(f0, f1);
    }
}

// ---------------------------------------------------------------------------
// Layer 3: a2 -> a3, s2 p1, relu((280-s)/16).
// Grid (imgg=64, qg=4, ob=2), CTA 128 = 4 warps; warp = 1 out-pixel q,
// lane = 2 images; 8 outs -> 8 ull accs.
// ---------------------------------------------------------------------------
__global__ __launch_bounds__(128, 6) void k_layer3(const float* __restrict__ a2,
                                                   const float* __restrict__ w3,
                                                   float* __restrict__ a3) {
    __shared__ __align__(16) ull wn[2304];  // [(c*9+k)*8+j] = dup2(-w3[(ob*8+j)*288+c*9+k])
    int t = threadIdx.x;
    int imgg = blockIdx.x, qg = blockIdx.y, ob = blockIdx.z;
    for (int i = t; i < 2304; i += 128) {
        int r = i >> 3, j = i & 7;
        wn[i] = dup2(-w3[(ob * 8 + j) * 288 + r]);
    }
    __syncthreads();

    int warp = t >> 5, lane = t & 31;
    int q = qg * 4 + warp;
    int qy = q >> 2, qx = q & 3;
    int b = imgg * 64 + lane * 2;

    int off[9];
#pragma unroll
    for (int kh = 0; kh < 3; kh++)
#pragma unroll
        for (int kw = 0; kw < 3; kw++) {
            int iy = qy * 2 - 1 + kh, ix = qx * 2 - 1 + kw;
            off[kh * 3 + kw] =
                (iy >= 0 && iy < 7 && ix >= 0 && ix < 7) ? (iy * 7 + ix) * B : -1;
        }

    ull s[8];
#pragma unroll
    for (int j = 0; j < 8; j++) s[j] = 0ULL;

    const float* base = a2 + b;
#pragma unroll 1
    for (int c = 0; c < 32; c++) {
        ull v[9];
#pragma unroll
        for (int k = 0; k < 9; k++)
            v[k] = (off[k] >= 0) ? *(const ull*)(base + c * (49 * B) + off[k]) : 0ULL;
#pragma unroll
        for (int k = 0; k < 9; k++) {
            const ulonglong2* wr = (const ulonglong2*)&wn[(c * 9 + k) * 8];
#pragma unroll
            for (int j2 = 0; j2 < 4; j2++) {
                ulonglong2 w = wr[j2];
                s[2 * j2]     = accabs(s[2 * j2],     v[k], w.x);
                s[2 * j2 + 1] = accabs(s[2 * j2 + 1], v[k], w.y);
            }
        }
    }

    float* op = a3 + ((ob * 8) * 16 + q) * B + b;
#pragma unroll
    for (int j = 0; j < 8; j++) {
        float f0 = fmaxf((280.0f - lo32(s[j])) * 0.0625f, 0.0f);
        float f1 = fmaxf((280.0f - hi32(s[j])) * 0.0625f, 0.0f);
        *(ull*)(op + j * (16 * B)) = pk2(f0, f1);
    }
}

// ---------------------------------------------------------------------------
// Layer 4 + log_softmax: a3 -> out[b][10]. Patch rows/cols 0..2 of 4x4.
// 8 threads per image-pair: csub = t&7 handles channels {2*csub, 2*csub+1};
// shfl_xor(1,2,4) reduces over csub; lane&7==0 does softmax for 2 images.
// Grid 64 CTAs x 256 thr (8x parallelism vs before).
// ---------------------------------------------------------------------------
__global__ __launch_bounds__(256) void k_layer4(const float* __restrict__ a3,
                                                const float* __restrict__ w4,
                                                float* __restrict__ out) {
    __shared__ __align__(16) ull wn[1440];  // [(c*9+k)*10+o] = dup2(-w4[o*144+c*9+k])
    int t = threadIdx.x;
    for (int i = t; i < 1440; i += 256) {
        int r = i / 10, o = i - r * 10;
        wn[i] = dup2(-w4[o * 144 + r]);
    }
    __syncthreads();

    int csub = t & 7;
    int pairIdx = t >> 3;                    // 0..31 per CTA
    int b = (blockIdx.x * 32 + pairIdx) * 2;

    ull acc[10];
#pragma unroll
    for (int o = 0; o < 10; o++) acc[o] = 0ULL;

    const float* base = a3 + b;
#pragma unroll
    for (int cc = 0; cc < 2; cc++) {
        int c = csub * 2 + cc;
#pragma unroll
        for (int kh = 0; kh < 3; kh++)
#pragma unroll
            for (int kw = 0; kw < 3; kw++) {
                ull v = *(const ull*)(base + (c * 16 + kh * 4 + kw) * B);
                const ull* wr = &wn[(c * 9 + kh * 3 + kw) * 10];
#pragma unroll
                for (int o2 = 0; o2 < 5; o2++) {
                    ulonglong2 w = *(const ulonglong2*)&wr[o2 * 2];
                    acc[2 * o2]     = accabs(acc[2 * o2],     v, w.x);
                    acc[2 * o2 + 1] = accabs(acc[2 * o2 + 1], v, w.y);
                }
            }
    }

    // reduce across csub (lane bits 0..2)
#pragma unroll
    for (int off = 1; off <= 4; off <<= 1)
#pragma unroll
        for (int o = 0; o < 10; o++)
            acc[o] = add2(acc[o], __shfl_xor_sync(0xffffffffu, acc[o], off));

    if (csub == 0) {
        float l0[10], l1[10];
#pragma unroll
        for (int o = 0; o < 10; o++) { l0[o] = -lo32(acc[o]); l1[o] = -hi32(acc[o]); }
        float m0 = l0[0], m1 = l1[0];
#pragma unroll
        for (int o = 1; o < 10; o++) { m0 = fmaxf(m0, l0[o]); m1 = fmaxf(m1, l1[o]); }
        float e0 = 0.0f, e1 = 0.0f;
#pragma unroll
        for (int o = 0; o < 10; o++) { e0 += expf(l0[o] - m0); e1 += expf(l1[o] - m1); }
        float d0 = m0 + logf(e0), d1 = m1 + logf(e1);

        ull* op0 = (ull*)(out + b * 10);
        ull* op1 = (ull*)(out + (b + 1) * 10);
#pragma unroll
        for (int o2 = 0; o2 < 5; o2++) {
            op0[o2] = pk2(l0[2 * o2] - d0, l0[2 * o2 + 1] - d0);
            op1[o2] = pk2(l1[2 * o2] - d1, l1[2 * o2 + 1] - d1);
        }
    }
}

// ---------------------------------------------------------------------------
extern "C" void kernel_launch(void* const* d_in, const int* in_sizes, int n_in,
                              void* d_out, int out_size) {
    const float* x  = (const float*)d_in[0];
    const float* w1 = (const float*)d_in[1];
    const float* w2 = (const float*)d_in[2];
    const float* w3 = (const float*)d_in[3];
    const float* w4 = (const float*)d_in[4];
    float* out = (float*)d_out;

    float *a1, *a2, *a3;
    cudaGetSymbolAddress((void**)&a1, g_a1);
    cudaGetSymbolAddress((void**)&a2, g_a2);
    cudaGetSymbolAddress((void**)&a3, g_a3);

    const int smem1 = 784 * 18 * 4 + 144 * 8;   // 57600 B
    cudaFuncSetAttribute(k_layer1, cudaFuncAttributeMaxDynamicSharedMemorySize,
                         smem1);

    k_layer1<<<B / 16, 256, smem1>>>(x, w1, a1);
    k_layer2<<<dim3(64, 7, 2), 224>>>(a1, w2, a2);
    k_layer3<<<dim3(64, 4, 2), 128>>>(a2, w3, a3);
    k_layer4<<<B / 64, 256>>>(a3, w4, out);
}

// round 8
// speedup vs baseline: 2.3316x; 1.0752x over previous
#include <cuda_runtime.h>
#include <math.h>

// AdderNet, batch-minor packed-f32x2, zero-halo padded intermediates.
#define B 4096
typedef unsigned long long ull;
#define ABSM 0x7FFFFFFF7FFFFFFFULL

__device__ __forceinline__ ull add2(ull a, ull b) {
    ull r; asm("add.rn.f32x2 %0,%1,%2;" : "=l"(r) : "l"(a), "l"(b)); return r;
}
__device__ __forceinline__ ull dup2(float v) {
    ull r; asm("mov.b64 %0,{%1,%1};" : "=l"(r) : "f"(v)); return r;
}
__device__ __forceinline__ ull pk2(float a, float b) {
    ull r; asm("mov.b64 %0,{%1,%2};" : "=l"(r) : "f"(a), "f"(b)); return r;
}
__device__ __forceinline__ float lo32(ull a) { return __uint_as_float((unsigned)a); }
__device__ __forceinline__ float hi32(ull a) { return __uint_as_float((unsigned)(a >> 32)); }
__device__ __forceinline__ ull accabs(ull acc, ull v, ull wneg) {
    return add2(acc, add2(v, wneg) & ABSM);
}

// Padded layouts; halo stays zero forever (globals are zero-init, never written).
__device__ float g_a1[16 * 15 * 15 * B];   // [c][y0..14][x0..14][b], interior 1..13
__device__ float g_a2[32 * 9 * 9 * B];     // [o][y0..8][x0..8][b],  interior 1..7
__device__ float g_a3[16 * 4 * 4 * B];     // [o][q][b], unpadded

// ---------------------------------------------------------------------------
// Layer 1: x[b][784] (-0.5) -> a1p (padded), s2 p0, relu((10-s)/4).
// CTA = 16 images; smem transpose xs[p][18]; thread = (pixel-slot, img-pair).
// ---------------------------------------------------------------------------
__global__ __launch_bounds__(256) void k_layer1(const float* __restrict__ x,
                                                const float* __restrict__ w1,
                                                float* __restrict__ a1) {
    extern __shared__ float dyn[];
    float* xs = dyn;                         // [784][18]
    ull* wn = (ull*)(dyn + 784 * 18);        // [k*16+o] = dup2(-w1[o*9+k])

    int t = threadIdx.x;
    int b0 = blockIdx.x * 16;
    if (t < 144) { int o = t / 9, k = t % 9; wn[k * 16 + o] = dup2(-w1[t]); }
    for (int i = t; i < 784 * 16; i += 256) {
        int img = i / 784, p = i - img * 784;
        xs[p * 18 + img] = x[(b0 + img) * 784 + p] - 0.5f;
    }
    __syncthreads();

    int i2 = t & 7;
    int slot = t >> 3;
    for (int pass = 0; pass < 6; pass++) {
        int pix = pass * 32 + slot;
        if (pix >= 169) break;
        int py = pix / 13, px = pix - py * 13;

        ull v[9];
#pragma unroll
        for (int kh = 0; kh < 3; kh++)
#pragma unroll
            for (int kw = 0; kw < 3; kw++)
                v[kh * 3 + kw] =
                    *(const ull*)&xs[((py * 2 + kh) * 28 + px * 2 + kw) * 18 + i2 * 2];

        ull acc[16];
#pragma unroll
        for (int c = 0; c < 16; c++) acc[c] = 0ULL;
#pragma unroll
        for (int k = 0; k < 9; k++) {
            const ulonglong2* wr = (const ulonglong2*)&wn[k * 16];
#pragma unroll
            for (int c2 = 0; c2 < 8; c2++) {
                ulonglong2 w = wr[c2];
                acc[2 * c2]     = accabs(acc[2 * c2],     v[k], w.x);
                acc[2 * c2 + 1] = accabs(acc[2 * c2 + 1], v[k], w.y);
            }
        }

        // write into padded interior (py+1, px+1)
        float* op = a1 + ((py + 1) * 15 + (px + 1)) * B + b0 + i2 * 2;
#pragma unroll
        for (int c = 0; c < 16; c++) {
            float f0 = fmaxf((10.0f - lo32(acc[c])) * 0.25f, 0.0f);
            float f1 = fmaxf((10.0f - hi32(acc[c])) * 0.25f, 0.0f);
            *(ull*)(op + c * (225 * B)) = pk2(f0, f1);
        }
    }
}

// ---------------------------------------------------------------------------
// Layer 2: a1p -> a2p, s2 p1, relu((130-s)/8).
// Grid (imgg=64, pixg=7, ob=2), CTA 224 = 7 warps; warp = out-pixel,
// lane = 2 images. Halo layout: taps are unconditional const-offset LDG.64.
// ---------------------------------------------------------------------------
__global__ __launch_bounds__(224, 4) void k_layer2(const float* __restrict__ a1,
                                                   const float* __restrict__ w2,
                                                   float* __restrict__ a2) {
    __shared__ __align__(16) ull wn[2304];  // [(c*9+k)*16+j] = dup2(-w2[(ob*16+j)*144+c*9+k])
    int t = threadIdx.x;
    int imgg = blockIdx.x, pixg = blockIdx.y, ob = blockIdx.z;
    for (int i = t; i < 2304; i += 224) {
        int r = i >> 4, j = i & 15;
        wn[i] = dup2(-w2[(ob * 16 + j) * 144 + r]);
    }
    __syncthreads();

    int warp = t >> 5, lane = t & 31;
    int pix = pixg * 7 + warp;          // 0..48
    int py = pix / 7, px = pix - py * 7;
    int b = imgg * 64 + lane * 2;

    // tap (kh,kw) at padded row py*2+kh, col px*2+kw
    const float* base = a1 + ((py * 2) * 15 + px * 2) * B + b;

    ull s[16];
#pragma unroll
    for (int j = 0; j < 16; j++) s[j] = 0ULL;

#pragma unroll 1
    for (int c = 0; c < 16; c++) {
        const float* bc = base + c * (225 * B);
        ull v[9];
#pragma unroll
        for (int kh = 0; kh < 3; kh++)
#pragma unroll
            for (int kw = 0; kw < 3; kw++)
                v[kh * 3 + kw] = *(const ull*)(bc + (kh * 15 + kw) * B);
#pragma unroll
        for (int k = 0; k < 9; k++) {
            const ulonglong2* wr = (const ulonglong2*)&wn[(c * 9 + k) * 16];
#pragma unroll
            for (int j2 = 0; j2 < 8; j2++) {
                ulonglong2 w = wr[j2];
                s[2 * j2]     = accabs(s[2 * j2],     v[k], w.x);
                s[2 * j2 + 1] = accabs(s[2 * j2 + 1], v[k], w.y);
            }
        }
    }

    // write padded interior (py+1, px+1)
    float* op = a2 + ((ob * 16) * 81 + (py + 1) * 9 + (px + 1)) * B + b;
#pragma unroll
    for (int j = 0; j < 16; j++) {
        float f0 = fmaxf((130.0f - lo32(s[j])) * 0.125f, 0.0f);
        float f1 = fmaxf((130.0f - hi32(s[j])) * 0.125f, 0.0f);
        *(ull*)(op + j * (81 * B)) = pk2(f0, f1);
    }
}

// ---------------------------------------------------------------------------
// Layer 3: a2p -> a3, s2 p1, relu((280-s)/16).
// Grid (imgg=64, qg=4, ob=2), CTA 128 = 4 warps; warp = out-pixel q,
// lane = 2 images; unconditional halo taps.
// ---------------------------------------------------------------------------
__global__ __launch_bounds__(128, 6) void k_layer3(const float* __restrict__ a2,
                                                   const float* __restrict__ w3,
                                                   float* __restrict__ a3) {
    __shared__ __align__(16) ull wn[2304];  // [(c*9+k)*8+j] = dup2(-w3[(ob*8+j)*288+c*9+k])
    int t = threadIdx.x;
    int imgg = blockIdx.x, qg = blockIdx.y, ob = blockIdx.z;
    for (int i = t; i < 2304; i += 128) {
        int r = i >> 3, j = i & 7;
        wn[i] = dup2(-w3[(ob * 8 + j) * 288 + r]);
    }
    __syncthreads();

    int warp = t >> 5, lane = t & 31;
    int q = qg * 4 + warp;
    int qy = q >> 2, qx = q & 3;
    int b = imgg * 64 + lane * 2;

    const float* base = a2 + ((qy * 2) * 9 + qx * 2) * B + b;

    ull s[8];
#pragma unroll
    for (int j = 0; j < 8; j++) s[j] = 0ULL;

#pragma unroll 1
    for (int c = 0; c < 32; c++) {
        const float* bc = base + c * (81 * B);
        ull v[9];
#pragma unroll
        for (int kh = 0; kh < 3; kh++)
#pragma unroll
            for (int kw = 0; kw < 3; kw++)
                v[kh * 3 + kw] = *(const ull*)(bc + (kh * 9 + kw) * B);
#pragma unroll
        for (int k = 0; k < 9; k++) {
            const ulonglong2* wr = (const ulonglong2*)&wn[(c * 9 + k) * 8];
#pragma unroll
            for (int j2 = 0; j2 < 4; j2++) {
                ulonglong2 w = wr[j2];
                s[2 * j2]     = accabs(s[2 * j2],     v[k], w.x);
                s[2 * j2 + 1] = accabs(s[2 * j2 + 1], v[k], w.y);
            }
        }
    }

    float* op = a3 + ((ob * 8) * 16 + q) * B + b;
#pragma unroll
    for (int j = 0; j < 8; j++) {
        float f0 = fmaxf((280.0f - lo32(s[j])) * 0.0625f, 0.0f);
        float f1 = fmaxf((280.0f - hi32(s[j])) * 0.0625f, 0.0f);
        *(ull*)(op + j * (16 * B)) = pk2(f0, f1);
    }
}

// ---------------------------------------------------------------------------
// Layer 4 + log_softmax: a3 -> out[b][10]. Patch rows/cols 0..2 of 4x4.
// 16 threads per image-pair (csub = 1 channel each); shfl_xor(1,2,4,8)
// reduce; csub==0 does softmax for 2 images. 256 CTAs x 128 thr.
// ---------------------------------------------------------------------------
__global__ __launch_bounds__(128) void k_layer4(const float* __restrict__ a3,
                                                const float* __restrict__ w4,
                                                float* __restrict__ out) {
    __shared__ __align__(16) ull wn[1440];  // [(c*9+k)*10+o] = dup2(-w4[o*144+c*9+k])
    int t = threadIdx.x;
    for (int i = t; i < 1440; i += 128) {
        int r = i / 10, o = i - r * 10;
        wn[i] = dup2(-w4[o * 144 + r]);
    }
    __syncthreads();

    int csub = t & 15;                 // channel
    int pairIdx = t >> 4;              // 0..7 per CTA
    int b = (blockIdx.x * 8 + pairIdx) * 2;

    ull acc[10];
#pragma unroll
    for (int o = 0; o < 10; o++) acc[o] = 0ULL;

    const float* base = a3 + b;
#pragma unroll
    for (int kh = 0; kh < 3; kh++)
#pragma unroll
        for (int kw = 0; kw < 3; kw++) {
            ull v = *(const ull*)(base + (csub * 16 + kh * 4 + kw) * B);
            const ull* wr = &wn[(csub * 9 + kh * 3 + kw) * 10];
#pragma unroll
            for (int o2 = 0; o2 < 5; o2++) {
                ulonglong2 w = *(const ulonglong2*)&wr[o2 * 2];
                acc[2 * o2]     = accabs(acc[2 * o2],     v, w.x);
                acc[2 * o2 + 1] = accabs(acc[2 * o2 + 1], v, w.y);
            }
        }

    // reduce across csub (lane bits 0..3)
#pragma unroll
    for (int off = 1; off <= 8; off <<= 1)
#pragma unroll
        for (int o = 0; o < 10; o++)
            acc[o] = add2(acc[o], __shfl_xor_sync(0xffffffffu, acc[o], off));

    if (csub == 0) {
        float l0[10], l1[10];
#pragma unroll
        for (int o = 0; o < 10; o++) { l0[o] = -lo32(acc[o]); l1[o] = -hi32(acc[o]); }
        float m0 = l0[0], m1 = l1[0];
#pragma unroll
        for (int o = 1; o < 10; o++) { m0 = fmaxf(m0, l0[o]); m1 = fmaxf(m1, l1[o]); }
        float e0 = 0.0f, e1 = 0.0f;
#pragma unroll
        for (int o = 0; o < 10; o++) { e0 += expf(l0[o] - m0); e1 += expf(l1[o] - m1); }
        float d0 = m0 + logf(e0), d1 = m1 + logf(e1);

        ull* op0 = (ull*)(out + b * 10);
        ull* op1 = (ull*)(out + (b + 1) * 10);
#pragma unroll
        for (int o2 = 0; o2 < 5; o2++) {
            op0[o2] = pk2(l0[2 * o2] - d0, l0[2 * o2 + 1] - d0);
            op1[o2] = pk2(l1[2 * o2] - d1, l1[2 * o2 + 1] - d1);
        }
    }
}

// ---------------------------------------------------------------------------
extern "C" void kernel_launch(void* const* d_in, const int* in_sizes, int n_in,
                              void* d_out, int out_size) {
    const float* x  = (const float*)d_in[0];
    const float* w1 = (const float*)d_in[1];
    const float* w2 = (const float*)d_in[2];
    const float* w3 = (const float*)d_in[3];
    const float* w4 = (const float*)d_in[4];
    float* out = (float*)d_out;

    float *a1, *a2, *a3;
    cudaGetSymbolAddress((void**)&a1, g_a1);
    cudaGetSymbolAddress((void**)&a2, g_a2);
    cudaGetSymbolAddress((void**)&a3, g_a3);

    const int smem1 = 784 * 18 * 4 + 144 * 8;   // 57600 B
    cudaFuncSetAttribute(k_layer1, cudaFuncAttributeMaxDynamicSharedMemorySize,
                         smem1);

    k_layer1<<<B / 16, 256, smem1>>>(x, w1, a1);
    k_layer2<<<dim3(64, 7, 2), 224>>>(a1, w2, a2);
    k_layer3<<<dim3(64, 4, 2), 128>>>(a2, w3, a3);
    k_layer4<<<B / 16, 128>>>(a3, w4, out);
}

// round 9
// speedup vs baseline: 2.3611x; 1.0126x over previous
#include <cuda_runtime.h>
#include <math.h>

// AdderNet, batch-minor packed-f32x2, zero-halo padded intermediates,
// software-pipelined channel loops.
#define B 4096
typedef unsigned long long ull;
#define ABSM 0x7FFFFFFF7FFFFFFFULL

__device__ __forceinline__ ull add2(ull a, ull b) {
    ull r; asm("add.rn.f32x2 %0,%1,%2;" : "=l"(r) : "l"(a), "l"(b)); return r;
}
__device__ __forceinline__ ull dup2(float v) {
    ull r; asm("mov.b64 %0,{%1,%1};" : "=l"(r) : "f"(v)); return r;
}
__device__ __forceinline__ ull pk2(float a, float b) {
    ull r; asm("mov.b64 %0,{%1,%2};" : "=l"(r) : "f"(a), "f"(b)); return r;
}
__device__ __forceinline__ float lo32(ull a) { return __uint_as_float((unsigned)a); }
__device__ __forceinline__ float hi32(ull a) { return __uint_as_float((unsigned)(a >> 32)); }
__device__ __forceinline__ ull accabs(ull acc, ull v, ull wneg) {
    return add2(acc, add2(v, wneg) & ABSM);
}

// Padded layouts; halo stays zero forever (globals zero-init, never written).
__device__ float g_a1[16 * 15 * 15 * B];   // [c][y][x][b], interior 1..13
__device__ float g_a2[32 * 9 * 9 * B];     // [o][y][x][b], interior 1..7
__device__ float g_a3[16 * 4 * 4 * B];     // [o][q][b]

// ---------------------------------------------------------------------------
// Layer 1: x[b][784] (-0.5) -> a1p, s2 p0, relu((10-s)/4).
// ---------------------------------------------------------------------------
__global__ __launch_bounds__(256) void k_layer1(const float* __restrict__ x,
                                                const float* __restrict__ w1,
                                                float* __restrict__ a1) {
    extern __shared__ float dyn[];
    float* xs = dyn;                         // [784][18]
    ull* wn = (ull*)(dyn + 784 * 18);        // [k*16+o] = dup2(-w1[o*9+k])

    int t = threadIdx.x;
    int b0 = blockIdx.x * 16;
    if (t < 144) { int o = t / 9, k = t % 9; wn[k * 16 + o] = dup2(-w1[t]); }
    for (int i = t; i < 784 * 16; i += 256) {
        int img = i / 784, p = i - img * 784;
        xs[p * 18 + img] = x[(b0 + img) * 784 + p] - 0.5f;
    }
    __syncthreads();

    int i2 = t & 7;
    int slot = t >> 3;
    for (int pass = 0; pass < 6; pass++) {
        int pix = pass * 32 + slot;
        if (pix >= 169) break;
        int py = pix / 13, px = pix - py * 13;

        ull v[9];
#pragma unroll
        for (int kh = 0; kh < 3; kh++)
#pragma unroll
            for (int kw = 0; kw < 3; kw++)
                v[kh * 3 + kw] =
                    *(const ull*)&xs[((py * 2 + kh) * 28 + px * 2 + kw) * 18 + i2 * 2];

        ull acc[16];
#pragma unroll
        for (int c = 0; c < 16; c++) acc[c] = 0ULL;
#pragma unroll
        for (int k = 0; k < 9; k++) {
            const ulonglong2* wr = (const ulonglong2*)&wn[k * 16];
#pragma unroll
            for (int c2 = 0; c2 < 8; c2++) {
                ulonglong2 w = wr[c2];
                acc[2 * c2]     = accabs(acc[2 * c2],     v[k], w.x);
                acc[2 * c2 + 1] = accabs(acc[2 * c2 + 1], v[k], w.y);
            }
        }

        float* op = a1 + ((py + 1) * 15 + (px + 1)) * B + b0 + i2 * 2;
#pragma unroll
        for (int c = 0; c < 16; c++) {
            float f0 = fmaxf((10.0f - lo32(acc[c])) * 0.25f, 0.0f);
            float f1 = fmaxf((10.0f - hi32(acc[c])) * 0.25f, 0.0f);
            *(ull*)(op + c * (225 * B)) = pk2(f0, f1);
        }
    }
}

// ---------------------------------------------------------------------------
// Layer 2: a1p -> a2p, s2 p1, relu((130-s)/8).
// Grid (64,7,2), CTA 224 = 7 warps; warp = out-pixel, lane = 2 images.
// Double-buffered taps: prefetch channel c+1 during compute of c.
// ---------------------------------------------------------------------------
__global__ __launch_bounds__(224, 3) void k_layer2(const float* __restrict__ a1,
                                                   const float* __restrict__ w2,
                                                   float* __restrict__ a2) {
    __shared__ __align__(16) ull wn[2304];  // [(c*9+k)*16+j] = dup2(-w2[(ob*16+j)*144+c*9+k])
    int t = threadIdx.x;
    int imgg = blockIdx.x, pixg = blockIdx.y, ob = blockIdx.z;
    for (int i = t; i < 2304; i += 224) {
        int r = i >> 4, j = i & 15;
        wn[i] = dup2(-w2[(ob * 16 + j) * 144 + r]);
    }
    __syncthreads();

    int warp = t >> 5, lane = t & 31;
    int pix = pixg * 7 + warp;
    int py = pix / 7, px = pix - py * 7;
    int b = imgg * 64 + lane * 2;

    const float* base = a1 + ((py * 2) * 15 + px * 2) * B + b;

    ull s[16];
#pragma unroll
    for (int j = 0; j < 16; j++) s[j] = 0ULL;

    ull v[9];
#pragma unroll
    for (int kh = 0; kh < 3; kh++)
#pragma unroll
        for (int kw = 0; kw < 3; kw++)
            v[kh * 3 + kw] = *(const ull*)(base + (kh * 15 + kw) * B);

#pragma unroll 1
    for (int c = 0; c < 15; c++) {
        ull vn[9];
        const float* bn = base + (c + 1) * (225 * B);
#pragma unroll
        for (int kh = 0; kh < 3; kh++)
#pragma unroll
            for (int kw = 0; kw < 3; kw++)
                vn[kh * 3 + kw] = *(const ull*)(bn + (kh * 15 + kw) * B);
#pragma unroll
        for (int k = 0; k < 9; k++) {
            const ulonglong2* wr = (const ulonglong2*)&wn[(c * 9 + k) * 16];
#pragma unroll
            for (int j2 = 0; j2 < 8; j2++) {
                ulonglong2 w = wr[j2];
                s[2 * j2]     = accabs(s[2 * j2],     v[k], w.x);
                s[2 * j2 + 1] = accabs(s[2 * j2 + 1], v[k], w.y);
            }
        }
#pragma unroll
        for (int k = 0; k < 9; k++) v[k] = vn[k];
    }
#pragma unroll
    for (int k = 0; k < 9; k++) {                 // final channel c=15
        const ulonglong2* wr = (const ulonglong2*)&wn[(15 * 9 + k) * 16];
#pragma unroll
        for (int j2 = 0; j2 < 8; j2++) {
            ulonglong2 w = wr[j2];
            s[2 * j2]     = accabs(s[2 * j2],     v[k], w.x);
            s[2 * j2 + 1] = accabs(s[2 * j2 + 1], v[k], w.y);
        }
    }

    float* op = a2 + ((ob * 16) * 81 + (py + 1) * 9 + (px + 1)) * B + b;
#pragma unroll
    for (int j = 0; j < 16; j++) {
        float f0 = fmaxf((130.0f - lo32(s[j])) * 0.125f, 0.0f);
        float f1 = fmaxf((130.0f - hi32(s[j])) * 0.125f, 0.0f);
        *(ull*)(op + j * (81 * B)) = pk2(f0, f1);
    }
}

// ---------------------------------------------------------------------------
// Layer 3: a2p -> a3, s2 p1, relu((280-s)/16).
// Grid (64,4,2), CTA 128 = 4 warps; warp = out-pixel q, lane = 2 images.
// Double-buffered taps.
// ---------------------------------------------------------------------------
__global__ __launch_bounds__(128, 6) void k_layer3(const float* __restrict__ a2,
                                                   const float* __restrict__ w3,
                                                   float* __restrict__ a3) {
    __shared__ __align__(16) ull wn[2304];  // [(c*9+k)*8+j] = dup2(-w3[(ob*8+j)*288+c*9+k])
    int t = threadIdx.x;
    int imgg = blockIdx.x, qg = blockIdx.y, ob = blockIdx.z;
    for (int i = t; i < 2304; i += 128) {
        int r = i >> 3, j = i & 7;
        wn[i] = dup2(-w3[(ob * 8 + j) * 288 + r]);
    }
    __syncthreads();

    int warp = t >> 5, lane = t & 31;
    int q = qg * 4 + warp;
    int qy = q >> 2, qx = q & 3;
    int b = imgg * 64 + lane * 2;

    const float* base = a2 + ((qy * 2) * 9 + qx * 2) * B + b;

    ull s[8];
#pragma unroll
    for (int j = 0; j < 8; j++) s[j] = 0ULL;

    ull v[9];
#pragma unroll
    for (int kh = 0; kh < 3; kh++)
#pragma unroll
        for (int kw = 0; kw < 3; kw++)
            v[kh * 3 + kw] = *(const ull*)(base + (kh * 9 + kw) * B);

#pragma unroll 1
    for (int c = 0; c < 31; c++) {
        ull vn[9];
        const float* bn = base + (c + 1) * (81 * B);
#pragma unroll
        for (int kh = 0; kh < 3; kh++)
#pragma unroll
            for (int kw = 0; kw < 3; kw++)
                vn[kh * 3 + kw] = *(const ull*)(bn + (kh * 9 + kw) * B);
#pragma unroll
        for (int k = 0; k < 9; k++) {
            const ulonglong2* wr = (const ulonglong2*)&wn[(c * 9 + k) * 8];
#pragma unroll
            for (int j2 = 0; j2 < 4; j2++) {
                ulonglong2 w = wr[j2];
                s[2 * j2]     = accabs(s[2 * j2],     v[k], w.x);
                s[2 * j2 + 1] = accabs(s[2 * j2 + 1], v[k], w.y);
            }
        }
#pragma unroll
        for (int k = 0; k < 9; k++) v[k] = vn[k];
    }
#pragma unroll
    for (int k = 0; k < 9; k++) {                 // final channel c=31
        const ulonglong2* wr = (const ulonglong2*)&wn[(31 * 9 + k) * 8];
#pragma unroll
        for (int j2 = 0; j2 < 4; j2++) {
            ulonglong2 w = wr[j2];
            s[2 * j2]     = accabs(s[2 * j2],     v[k], w.x);
            s[2 * j2 + 1] = accabs(s[2 * j2 + 1], v[k], w.y);
        }
    }

    float* op = a3 + ((ob * 8) * 16 + q) * B + b;
#pragma unroll
    for (int j = 0; j < 8; j++) {
        float f0 = fmaxf((280.0f - lo32(s[j])) * 0.0625f, 0.0f);
        float f1 = fmaxf((280.0f - hi32(s[j])) * 0.0625f, 0.0f);
        *(ull*)(op + j * (16 * B)) = pk2(f0, f1);
    }
}

// ---------------------------------------------------------------------------
// Layer 4 + log_softmax, scalar: 1 image/thread-group-of-16.
// Thread = (img, csub); csub = t&15 handles channel csub; shfl_xor(1,2,4,8)
// reduces; csub==0 does softmax. 64K threads = 2048 warps (~14/SM).
// ---------------------------------------------------------------------------
__global__ __launch_bounds__(256) void k_layer4(const float* __restrict__ a3,
                                                const float* __restrict__ w4,
                                                float* __restrict__ out) {
    __shared__ float wn[1440];  // [(c*9+k)*10+o] = -w4[o*144+c*9+k]
    int t = threadIdx.x;
    for (int i = t; i < 1440; i += 256) {
        int r = i / 10, o = i - r * 10;
        wn[i] = -w4[o * 144 + r];
    }
    __syncthreads();

    int csub = t & 15;
    int img = blockIdx.x * 16 + (t >> 4);

    float acc[10];
#pragma unroll
    for (int o = 0; o < 10; o++) acc[o] = 0.0f;

    const float* base = a3 + img;
#pragma unroll
    for (int kh = 0; kh < 3; kh++)
#pragma unroll
        for (int kw = 0; kw < 3; kw++) {
            float v = base[(csub * 16 + kh * 4 + kw) * B];
            const float* wr = &wn[(csub * 9 + kh * 3 + kw) * 10];
#pragma unroll
            for (int o = 0; o < 10; o++)
                acc[o] += fabsf(v + wr[o]);
        }

    // reduce across csub (lane bits 0..3)
#pragma unroll
    for (int off = 1; off <= 8; off <<= 1)
#pragma unroll
        for (int o = 0; o < 10; o++)
            acc[o] += __shfl_xor_sync(0xffffffffu, acc[o], off);

    if (csub == 0) {
        float l[10];
#pragma unroll
        for (int o = 0; o < 10; o++) l[o] = -acc[o];
        float m = l[0];
#pragma unroll
        for (int o = 1; o < 10; o++) m = fmaxf(m, l[o]);
        float e = 0.0f;
#pragma unroll
        for (int o = 0; o < 10; o++) e += expf(l[o] - m);
        float d = m + logf(e);

        ull* op = (ull*)(out + img * 10);   // 40B, 8B-aligned
#pragma unroll
        for (int o2 = 0; o2 < 5; o2++)
            op[o2] = pk2(l[2 * o2] - d, l[2 * o2 + 1] - d);
    }
}

// ---------------------------------------------------------------------------
extern "C" void kernel_launch(void* const* d_in, const int* in_sizes, int n_in,
                              void* d_out, int out_size) {
    const float* x  = (const float*)d_in[0];
    const float* w1 = (const float*)d_in[1];
    const float* w2 = (const float*)d_in[2];
    const float* w3 = (const float*)d_in[3];
    const float* w4 = (const float*)d_in[4];
    float* out = (float*)d_out;

    float *a1, *a2, *a3;
    cudaGetSymbolAddress((void**)&a1, g_a1);
    cudaGetSymbolAddress((void**)&a2, g_a2);
    cudaGetSymbolAddress((void**)&a3, g_a3);

    const int smem1 = 784 * 18 * 4 + 144 * 8;   // 57600 B
    cudaFuncSetAttribute(k_layer1, cudaFuncAttributeMaxDynamicSharedMemorySize,
                         smem1);

    k_layer1<<<B / 16, 256, smem1>>>(x, w1, a1);
    k_layer2<<<dim3(64, 7, 2), 224>>>(a1, w2, a2);
    k_layer3<<<dim3(64, 4, 2), 128>>>(a2, w3, a3);
    k_layer4<<<B / 16, 256>>>(a3, w4, out);
}

// round 10
// speedup vs baseline: 2.8238x; 1.1960x over previous
#include <cuda_runtime.h>
#include <math.h>

// AdderNet, batch-minor, zero-halo padded intermediates.
// Inner math: d = fma(x, 2.0, -2w); acc = fma(|d|, 0.5, acc)  -- both
// FFMA-imm (rt_SMSP=1, 2x the FADD rate), exact scalings => bit-identical.
#define B 4096
typedef unsigned long long ull;

__device__ __forceinline__ ull pk2(float a, float b) {
    ull r; asm("mov.b64 %0,{%1,%2};" : "=l"(r) : "f"(a), "f"(b)); return r;
}
// one |x-w| accumulation via two FFMA-imm
__device__ __forceinline__ void AB(float& acc, float v, float wn2) {
    float d = __fmaf_rn(v, 2.0f, wn2);          // 2(x-w)
    acc = __fmaf_rn(fabsf(d), 0.5f, acc);       // acc += |x-w|
}

// Padded layouts; halo stays zero forever (globals zero-init, never written).
__device__ float g_a1[16 * 15 * 15 * B];   // [c][y][x][b], interior 1..13
__device__ float g_a2[32 * 9 * 9 * B];     // [o][y][x][b], interior 1..7
__device__ float g_a3[16 * 4 * 4 * B];     // [o][q][b]

// ---------------------------------------------------------------------------
// Layer 1: x[b][784] (-0.5) -> a1p, s2 p0, relu((10-s)/4).
// CTA = 16 images, smem transpose xs[p][18]; thread = (pixel-slot, img-pair).
// ---------------------------------------------------------------------------
__global__ __launch_bounds__(256) void k_layer1(const float* __restrict__ x,
                                                const float* __restrict__ w1,
                                                float* __restrict__ a1) {
    extern __shared__ float dyn[];
    float* xs = dyn;                     // [784][18]
    float* wn = dyn + 784 * 18;          // [k*16+o] = -2*w1[o*9+k]

    int t = threadIdx.x;
    int b0 = blockIdx.x * 16;
    if (t < 144) { int o = t / 9, k = t % 9; wn[k * 16 + o] = -2.0f * w1[t]; }
    for (int i = t; i < 784 * 16; i += 256) {
        int img = i / 784, p = i - img * 784;
        xs[p * 18 + img] = x[(b0 + img) * 784 + p] - 0.5f;
    }
    __syncthreads();

    int i2 = t & 7;
    int slot = t >> 3;
    for (int pass = 0; pass < 6; pass++) {
        int pix = pass * 32 + slot;
        if (pix >= 169) break;
        int py = pix / 13, px = pix - py * 13;

        float2 v[9];
#pragma unroll
        for (int kh = 0; kh < 3; kh++)
#pragma unroll
            for (int kw = 0; kw < 3; kw++)
                v[kh * 3 + kw] =
                    *(const float2*)&xs[((py * 2 + kh) * 28 + px * 2 + kw) * 18 + i2 * 2];

        float s0[16], s1[16];
#pragma unroll
        for (int c = 0; c < 16; c++) { s0[c] = 0.0f; s1[c] = 0.0f; }
#pragma unroll
        for (int k = 0; k < 9; k++) {
            const float4* wr = (const float4*)&wn[k * 16];
#pragma unroll
            for (int j4 = 0; j4 < 4; j4++) {
                float4 w = wr[j4];
                AB(s0[j4 * 4 + 0], v[k].x, w.x); AB(s1[j4 * 4 + 0], v[k].y, w.x);
                AB(s0[j4 * 4 + 1], v[k].x, w.y); AB(s1[j4 * 4 + 1], v[k].y, w.y);
                AB(s0[j4 * 4 + 2], v[k].x, w.z); AB(s1[j4 * 4 + 2], v[k].y, w.z);
                AB(s0[j4 * 4 + 3], v[k].x, w.w); AB(s1[j4 * 4 + 3], v[k].y, w.w);
            }
        }

        float* op = a1 + ((py + 1) * 15 + (px + 1)) * B + b0 + i2 * 2;
#pragma unroll
        for (int c = 0; c < 16; c++) {
            float f0 = fmaxf((10.0f - s0[c]) * 0.25f, 0.0f);
            float f1 = fmaxf((10.0f - s1[c]) * 0.25f, 0.0f);
            *(ull*)(op + c * (225 * B)) = pk2(f0, f1);
        }
    }
}

// ---------------------------------------------------------------------------
// Layer 2: a1p -> a2p, s2 p1, relu((130-s)/8).
// Grid (64,7,2), CTA 224 = 7 warps; warp = out-pixel, lane = 2 images.
// ---------------------------------------------------------------------------
__global__ __launch_bounds__(224, 3) void k_layer2(const float* __restrict__ a1,
                                                   const float* __restrict__ w2,
                                                   float* __restrict__ a2) {
    __shared__ __align__(16) float wn[2304];  // [(c*9+k)*16+j] = -2*w2[(ob*16+j)*144+c*9+k]
    int t = threadIdx.x;
    int imgg = blockIdx.x, pixg = blockIdx.y, ob = blockIdx.z;
    for (int i = t; i < 2304; i += 224) {
        int r = i >> 4, j = i & 15;
        wn[i] = -2.0f * w2[(ob * 16 + j) * 144 + r];
    }
    __syncthreads();

    int warp = t >> 5, lane = t & 31;
    int pix = pixg * 7 + warp;
    int py = pix / 7, px = pix - py * 7;
    int b = imgg * 64 + lane * 2;

    const float* base = a1 + ((py * 2) * 15 + px * 2) * B + b;

    float s0[16], s1[16];
#pragma unroll
    for (int j = 0; j < 16; j++) { s0[j] = 0.0f; s1[j] = 0.0f; }

#pragma unroll 1
    for (int c = 0; c < 16; c++) {
        const float* bc = base + c * (225 * B);
        float2 v[9];
#pragma unroll
        for (int kh = 0; kh < 3; kh++)
#pragma unroll
            for (int kw = 0; kw < 3; kw++)
                v[kh * 3 + kw] = *(const float2*)(bc + (kh * 15 + kw) * B);
#pragma unroll
        for (int k = 0; k < 9; k++) {
            const float4* wr = (const float4*)&wn[(c * 9 + k) * 16];
#pragma unroll
            for (int j4 = 0; j4 < 4; j4++) {
                float4 w = wr[j4];
                AB(s0[j4 * 4 + 0], v[k].x, w.x); AB(s1[j4 * 4 + 0], v[k].y, w.x);
                AB(s0[j4 * 4 + 1], v[k].x, w.y); AB(s1[j4 * 4 + 1], v[k].y, w.y);
                AB(s0[j4 * 4 + 2], v[k].x, w.z); AB(s1[j4 * 4 + 2], v[k].y, w.z);
                AB(s0[j4 * 4 + 3], v[k].x, w.w); AB(s1[j4 * 4 + 3], v[k].y, w.w);
            }
        }
    }

    float* op = a2 + ((ob * 16) * 81 + (py + 1) * 9 + (px + 1)) * B + b;
#pragma unroll
    for (int j = 0; j < 16; j++) {
        float f0 = fmaxf((130.0f - s0[j]) * 0.125f, 0.0f);
        float f1 = fmaxf((130.0f - s1[j]) * 0.125f, 0.0f);
        *(ull*)(op + j * (81 * B)) = pk2(f0, f1);
    }
}

// ---------------------------------------------------------------------------
// Layer 3: a2p -> a3, s2 p1, relu((280-s)/16).
// Grid (64,4,2), CTA 128 = 4 warps; warp = out-pixel q, lane = 2 images.
// ---------------------------------------------------------------------------
__global__ __launch_bounds__(128, 6) void k_layer3(const float* __restrict__ a2,
                                                   const float* __restrict__ w3,
                                                   float* __restrict__ a3) {
    __shared__ __align__(16) float wn[2304];  // [(c*9+k)*8+j] = -2*w3[(ob*8+j)*288+c*9+k]
    int t = threadIdx.x;
    int imgg = blockIdx.x, qg = blockIdx.y, ob = blockIdx.z;
    for (int i = t; i < 2304; i += 128) {
        int r = i >> 3, j = i & 7;
        wn[i] = -2.0f * w3[(ob * 8 + j) * 288 + r];
    }
    __syncthreads();

    int warp = t >> 5, lane = t & 31;
    int q = qg * 4 + warp;
    int qy = q >> 2, qx = q & 3;
    int b = imgg * 64 + lane * 2;

    const float* base = a2 + ((qy * 2) * 9 + qx * 2) * B + b;

    float s0[8], s1[8];
#pragma unroll
    for (int j = 0; j < 8; j++) { s0[j] = 0.0f; s1[j] = 0.0f; }

#pragma unroll 1
    for (int c = 0; c < 32; c++) {
        const float* bc = base + c * (81 * B);
        float2 v[9];
#pragma unroll
        for (int kh = 0; kh < 3; kh++)
#pragma unroll
            for (int kw = 0; kw < 3; kw++)
                v[kh * 3 + kw] = *(const float2*)(bc + (kh * 9 + kw) * B);
#pragma unroll
        for (int k = 0; k < 9; k++) {
            const float4* wr = (const float4*)&wn[(c * 9 + k) * 8];
#pragma unroll
            for (int j4 = 0; j4 < 2; j4++) {
                float4 w = wr[j4];
                AB(s0[j4 * 4 + 0], v[k].x, w.x); AB(s1[j4 * 4 + 0], v[k].y, w.x);
                AB(s0[j4 * 4 + 1], v[k].x, w.y); AB(s1[j4 * 4 + 1], v[k].y, w.y);
                AB(s0[j4 * 4 + 2], v[k].x, w.z); AB(s1[j4 * 4 + 2], v[k].y, w.z);
                AB(s0[j4 * 4 + 3], v[k].x, w.w); AB(s1[j4 * 4 + 3], v[k].y, w.w);
            }
        }
    }

    float* op = a3 + ((ob * 8) * 16 + q) * B + b;
#pragma unroll
    for (int j = 0; j < 8; j++) {
        float f0 = fmaxf((280.0f - s0[j]) * 0.0625f, 0.0f);
        float f1 = fmaxf((280.0f - s1[j]) * 0.0625f, 0.0f);
        *(ull*)(op + j * (16 * B)) = pk2(f0, f1);
    }
}

// ---------------------------------------------------------------------------
// Layer 4 + log_softmax: 1 image per 16-thread group (csub = channel),
// shfl_xor(1,2,4,8) reduce, csub==0 does softmax.
// ---------------------------------------------------------------------------
__global__ __launch_bounds__(256) void k_layer4(const float* __restrict__ a3,
                                                const float* __restrict__ w4,
                                                float* __restrict__ out) {
    __shared__ float wn[1440];  // [(c*9+k)*10+o] = -2*w4[o*144+c*9+k]
    int t = threadIdx.x;
    for (int i = t; i < 1440; i += 256) {
        int r = i / 10, o = i - r * 10;
        wn[i] = -2.0f * w4[o * 144 + r];
    }
    __syncthreads();

    int csub = t & 15;
    int img = blockIdx.x * 16 + (t >> 4);

    float acc[10];
#pragma unroll
    for (int o = 0; o < 10; o++) acc[o] = 0.0f;

    const float* base = a3 + img;
#pragma unroll
    for (int kh = 0; kh < 3; kh++)
#pragma unroll
        for (int kw = 0; kw < 3; kw++) {
            float v = base[(csub * 16 + kh * 4 + kw) * B];
            const float* wr = &wn[(csub * 9 + kh * 3 + kw) * 10];
#pragma unroll
            for (int o = 0; o < 10; o++)
                AB(acc[o], v, wr[o]);
        }

#pragma unroll
    for (int off = 1; off <= 8; off <<= 1)
#pragma unroll
        for (int o = 0; o < 10; o++)
            acc[o] += __shfl_xor_sync(0xffffffffu, acc[o], off);

    if (csub == 0) {
        float l[10];
#pragma unroll
        for (int o = 0; o < 10; o++) l[o] = -acc[o];
        float m = l[0];
#pragma unroll
        for (int o = 1; o < 10; o++) m = fmaxf(m, l[o]);
        float e = 0.0f;
#pragma unroll
        for (int o = 0; o < 10; o++) e += expf(l[o] - m);
        float d = m + logf(e);

        ull* op = (ull*)(out + img * 10);
#pragma unroll
        for (int o2 = 0; o2 < 5; o2++)
            op[o2] = pk2(l[2 * o2] - d, l[2 * o2 + 1] - d);
    }
}

// ---------------------------------------------------------------------------
extern "C" void kernel_launch(void* const* d_in, const int* in_sizes, int n_in,
                              void* d_out, int out_size) {
    const float* x  = (const float*)d_in[0];
    const float* w1 = (const float*)d_in[1];
    const float* w2 = (const float*)d_in[2];
    const float* w3 = (const float*)d_in[3];
    const float* w4 = (const float*)d_in[4];
    float* out = (float*)d_out;

    float *a1, *a2, *a3;
    cudaGetSymbolAddress((void**)&a1, g_a1);
    cudaGetSymbolAddress((void**)&a2, g_a2);
    cudaGetSymbolAddress((void**)&a3, g_a3);

    const int smem1 = 784 * 18 * 4 + 144 * 4;   // 57024 B
    cudaFuncSetAttribute(k_layer1, cudaFuncAttributeMaxDynamicSharedMemorySize,
                         smem1);

    k_layer1<<<B / 16, 256, smem1>>>(x, w1, a1);
    k_layer2<<<dim3(64, 7, 2), 224>>>(a1, w2, a2);
    k_layer3<<<dim3(64, 4, 2), 128>>>(a2, w3, a3);
    k_layer4<<<B / 16, 256>>>(a3, w4, out);
}